// round 14
// baseline (speedup 1.0000x reference)
#include <cuda_runtime.h>
#include <cuda_bf16.h>

// CovarianceResidualError, grid-stride stream with HOISTED a-values:
//   a_i = graph_emb[i,0];  ACC_j = sum_i e_ij*a_i;  SE_j = sum_i e_ij;  SA = sum_i a_i
//   out = -sum_j |ACC_j - SA*SE_j/N|
//
// All prior variants pinned at ~5TB/s; the remaining serial dependency was
// the per-step scattered a-load -> shfl -> FMA chain inside the hot loop.
// Here each warp preloads its 64 a-values into 2 registers/lane up front;
// the loop body is then a pure e-stream (LDG.128 + FMA) with register-shfl
// broadcast only. Deterministic int64 (2^40) atomic combine; ticket-elected
// last CTA finalizes and re-zeros for the next graph replay.

#define NROWS 131072
#define OCOLS 256
#define DCOLS 128
#define NB 512
#define NSTEPS 64

#define SCALE    1099511627776.0f          // 2^40
#define INVSCALE (1.0 / 1099511627776.0)

__device__ unsigned long long g_iacc[OCOLS];
__device__ unsigned long long g_ise [OCOLS];
__device__ unsigned long long g_isa;
__device__ unsigned int g_ct = 0;

__device__ __forceinline__ unsigned long long q40(float v) {
    return (unsigned long long)(long long)llrintf(v * SCALE);
}

__global__ void __launch_bounds__(256, 4)
cov_kernel(const float* __restrict__ ge, const float4* __restrict__ err4,
           float* __restrict__ out)
{
    __shared__ float red[4 * OCOLS];
    __shared__ float ssa[4];
    __shared__ unsigned int s_ticket;

    const int tid = threadIdx.x;
    const int w   = tid >> 5;          // warp 0..7
    const int l   = tid & 31;          // lane
    const int bid = blockIdx.x;
    const size_t gth = (size_t)bid * 256 + tid;   // global thread id

    // Warp covers half a row per step; row at step k = rowbase + k*2048.
    const int rowbase = bid * 4 + (w >> 1);

    // ---- hoisted a-values: lane t holds steps t and t+32 ----
    const float a_lo = __ldcs(&ge[(size_t)(rowbase + l * 2048) * DCOLS]);
    const float a_hi = __ldcs(&ge[(size_t)(rowbase + (l + 32) * 2048) * DCOLS]);

    float4 acc = make_float4(0.f, 0.f, 0.f, 0.f);
    float4 se  = make_float4(0.f, 0.f, 0.f, 0.f);

    // ---- pure e-stream: one 2MB chip-wide window per step ----
    #pragma unroll 16
    for (int k = 0; k < NSTEPS; ++k) {
        const float a = (k < 32) ? __shfl_sync(0xffffffffu, a_lo, k)
                                 : __shfl_sync(0xffffffffu, a_hi, k - 32);
        const float4 e = __ldcs(&err4[gth + (size_t)k * ((size_t)NROWS * (OCOLS / 4) / NSTEPS)]);
        acc.x = fmaf(e.x, a, acc.x); acc.y = fmaf(e.y, a, acc.y);
        acc.z = fmaf(e.z, a, acc.z); acc.w = fmaf(e.w, a, acc.w);
        se.x += e.x; se.y += e.y; se.z += e.z; se.w += e.w;
    }

    // ---- SA partials from preloaded regs (even warps own rows) ----
    if ((w & 1) == 0) {
        float sa = a_lo + a_hi;                       // 2 rows per lane
        #pragma unroll
        for (int off = 16; off > 0; off >>= 1)
            sa += __shfl_down_sync(0xffffffffu, sa, off);
        if (l == 0) ssa[w >> 1] = sa;
    }

    // ---- reduce 4 row-phases per column group (deterministic, via shared) ----
    const int tx = tid & 63;
    const int ty = tid >> 6;
    __syncthreads();
    red[ty * OCOLS + 4 * tx + 0] = acc.x;
    red[ty * OCOLS + 4 * tx + 1] = acc.y;
    red[ty * OCOLS + 4 * tx + 2] = acc.z;
    red[ty * OCOLS + 4 * tx + 3] = acc.w;
    __syncthreads();
    const float accTot =
        red[tid] + red[OCOLS + tid] + red[2 * OCOLS + tid] + red[3 * OCOLS + tid];
    __syncthreads();
    red[ty * OCOLS + 4 * tx + 0] = se.x;
    red[ty * OCOLS + 4 * tx + 1] = se.y;
    red[ty * OCOLS + 4 * tx + 2] = se.z;
    red[ty * OCOLS + 4 * tx + 3] = se.w;
    __syncthreads();
    const float seTot =
        red[tid] + red[OCOLS + tid] + red[2 * OCOLS + tid] + red[3 * OCOLS + tid];

    // Deterministic global accumulation (order-independent integer adds)
    atomicAdd(&g_iacc[tid], q40(accTot));
    atomicAdd(&g_ise [tid], q40(seTot));
    if (tid == 0)
        atomicAdd(&g_isa, q40(ssa[0] + ssa[1] + ssa[2] + ssa[3]));

    __syncthreads();
    if (tid == 0) {
        __threadfence();
        s_ticket = atomicAdd(&g_ct, 1u);
    }
    __syncthreads();

    // ---- last-finishing CTA finalizes ----
    if (s_ticket == NB - 1) {
        __threadfence();
        const double A = (double)(long long)g_iacc[tid] * INVSCALE;
        const double S = (double)(long long)g_ise [tid] * INVSCALE;
        const double kk = ((double)(long long)g_isa * INVSCALE) / (double)NROWS;

        red[tid] = (float)fabs(A - kk * S);
        __syncthreads();
        #pragma unroll
        for (int st = 128; st > 0; st >>= 1) {
            if (tid < st) red[tid] += red[tid + st];
            __syncthreads();
        }
        if (tid == 0) out[0] = -red[0];

        // re-zero for the next graph replay
        g_iacc[tid] = 0ull;
        g_ise [tid] = 0ull;
        if (tid == 0) { g_isa = 0ull; g_ct = 0u; }
        __threadfence();
    }
}

extern "C" void kernel_launch(void* const* d_in, const int* in_sizes, int n_in,
                              void* d_out, int out_size)
{
    const float* ge  = nullptr;   // graph_emb (N x 128)
    const float* err = nullptr;   // errors    (N x 256)
    for (int i = 0; i < n_in; ++i) {
        if (in_sizes[i] == NROWS * DCOLS) ge  = (const float*)d_in[i];
        else if (in_sizes[i] == NROWS * OCOLS) err = (const float*)d_in[i];
    }

    cov_kernel<<<NB, 256>>>(ge, (const float4*)err, (float*)d_out);
}

// round 15
// speedup vs baseline: 1.4627x; 1.4627x over previous
#include <cuda_runtime.h>
#include <cuda_bf16.h>

// CovarianceResidualError, grid-stride stream, DUAL ROW-STREAMS per thread:
//   a_i = graph_emb[i,0];  ACC_j = sum_i e_ij*a_i;  SE_j = sum_i e_ij;  SA = sum_i a_i
//   out = -sum_j |ACC_j - SA*SE_j/N|
//
// R14 proved we're in the lat/MLP_eff regime (reg collapse 64->28 halved BW).
// Here each thread carries TWO independent row streams with separate
// accumulators (16 accum regs) -> ~2x batched LDG.128 in flight (MLP_eff ~16).
// Whole chip sweeps one contiguous 4096-row window per step. Deterministic
// int64 (2^40) atomic combine; ticket-elected last CTA finalizes + re-zeros.

#define NROWS 131072
#define OCOLS 256
#define DCOLS 128
#define NB 512
#define NSTEPS 32                          // 131072 rows / (512 CTA * 8 rows)

#define SCALE    1099511627776.0f          // 2^40
#define INVSCALE (1.0 / 1099511627776.0)

__device__ unsigned long long g_iacc[OCOLS];
__device__ unsigned long long g_ise [OCOLS];
__device__ unsigned long long g_isa;
__device__ unsigned int g_ct = 0;

__device__ __forceinline__ unsigned long long q40(float v) {
    return (unsigned long long)(long long)llrintf(v * SCALE);
}

__global__ void __launch_bounds__(256, 4)
cov_kernel(const float* __restrict__ ge, const float4* __restrict__ err4,
           float* __restrict__ out)
{
    __shared__ float red[4 * OCOLS];
    __shared__ float ssa[4];
    __shared__ unsigned int s_ticket;

    const int tid = threadIdx.x;
    const int w   = tid >> 5;          // warp 0..7
    const int l   = tid & 31;          // lane
    const int tx  = tid & 63;          // column group (fixed all kernel)
    const int ty  = tid >> 6;          // row phase 0..3
    const int bid = blockIdx.x;

    // CTA's 8-row sub-window base within each step window
    const int rbase = bid * 8;

    float4 acc1 = make_float4(0.f,0.f,0.f,0.f), acc2 = acc1;
    float4 se1  = acc1, se2 = acc1;
    float  sa   = 0.f;

    #pragma unroll 4
    for (int k = 0; k < NSTEPS; ++k) {
        const int row = k * 4096 + rbase + ty;        // stream 1: row ty
        // a-values for rows (ty, ty+4): lanes 0/1 load, broadcast
        float av = 0.f;
        if (l < 2)
            av = __ldcs(&ge[(size_t)(row + 4 * l) * DCOLS]);
        const float a1 = __shfl_sync(0xffffffffu, av, 0);
        const float a2 = __shfl_sync(0xffffffffu, av, 1);

        const float4 e1 = __ldcs(&err4[(size_t)row * (OCOLS / 4) + tx]);
        const float4 e2 = __ldcs(&err4[(size_t)(row + 4) * (OCOLS / 4) + tx]);

        acc1.x = fmaf(e1.x, a1, acc1.x); acc1.y = fmaf(e1.y, a1, acc1.y);
        acc1.z = fmaf(e1.z, a1, acc1.z); acc1.w = fmaf(e1.w, a1, acc1.w);
        se1.x += e1.x; se1.y += e1.y; se1.z += e1.z; se1.w += e1.w;

        acc2.x = fmaf(e2.x, a2, acc2.x); acc2.y = fmaf(e2.y, a2, acc2.y);
        acc2.z = fmaf(e2.z, a2, acc2.z); acc2.w = fmaf(e2.w, a2, acc2.w);
        se2.x += e2.x; se2.y += e2.y; se2.z += e2.z; se2.w += e2.w;

        if ((w & 1) == 0) sa += a1 + a2;   // rows counted once (even warps)
    }

    // merge dual streams
    float4 acc = make_float4(acc1.x + acc2.x, acc1.y + acc2.y,
                             acc1.z + acc2.z, acc1.w + acc2.w);
    float4 se  = make_float4(se1.x + se2.x, se1.y + se2.y,
                             se1.z + se2.z, se1.w + se2.w);

    // ---- SA partials: lane0 of even warps ----
    if ((w & 1) == 0 && l == 0) ssa[w >> 1] = sa;

    // ---- reduce 4 row-phases per column group (deterministic, via shared) ----
    __syncthreads();
    red[ty * OCOLS + 4 * tx + 0] = acc.x;
    red[ty * OCOLS + 4 * tx + 1] = acc.y;
    red[ty * OCOLS + 4 * tx + 2] = acc.z;
    red[ty * OCOLS + 4 * tx + 3] = acc.w;
    __syncthreads();
    const float accTot =
        red[tid] + red[OCOLS + tid] + red[2 * OCOLS + tid] + red[3 * OCOLS + tid];
    __syncthreads();
    red[ty * OCOLS + 4 * tx + 0] = se.x;
    red[ty * OCOLS + 4 * tx + 1] = se.y;
    red[ty * OCOLS + 4 * tx + 2] = se.z;
    red[ty * OCOLS + 4 * tx + 3] = se.w;
    __syncthreads();
    const float seTot =
        red[tid] + red[OCOLS + tid] + red[2 * OCOLS + tid] + red[3 * OCOLS + tid];

    // Deterministic global accumulation (order-independent integer adds)
    atomicAdd(&g_iacc[tid], q40(accTot));
    atomicAdd(&g_ise [tid], q40(seTot));
    if (tid == 0)
        atomicAdd(&g_isa, q40(ssa[0] + ssa[1] + ssa[2] + ssa[3]));

    __syncthreads();
    if (tid == 0) {
        __threadfence();
        s_ticket = atomicAdd(&g_ct, 1u);
    }
    __syncthreads();

    // ---- last-finishing CTA finalizes ----
    if (s_ticket == NB - 1) {
        __threadfence();
        const double A = (double)(long long)g_iacc[tid] * INVSCALE;
        const double S = (double)(long long)g_ise [tid] * INVSCALE;
        const double kk = ((double)(long long)g_isa * INVSCALE) / (double)NROWS;

        red[tid] = (float)fabs(A - kk * S);
        __syncthreads();
        #pragma unroll
        for (int st = 128; st > 0; st >>= 1) {
            if (tid < st) red[tid] += red[tid + st];
            __syncthreads();
        }
        if (tid == 0) out[0] = -red[0];

        // re-zero for the next graph replay
        g_iacc[tid] = 0ull;
        g_ise [tid] = 0ull;
        if (tid == 0) { g_isa = 0ull; g_ct = 0u; }
        __threadfence();
    }
}

extern "C" void kernel_launch(void* const* d_in, const int* in_sizes, int n_in,
                              void* d_out, int out_size)
{
    const float* ge  = nullptr;   // graph_emb (N x 128)
    const float* err = nullptr;   // errors    (N x 256)
    for (int i = 0; i < n_in; ++i) {
        if (in_sizes[i] == NROWS * DCOLS) ge  = (const float*)d_in[i];
        else if (in_sizes[i] == NROWS * OCOLS) err = (const float*)d_in[i];
    }

    cov_kernel<<<NB, 256>>>(ge, (const float4*)err, (float*)d_out);
}